// round 7
// baseline (speedup 1.0000x reference)
#include <cuda_runtime.h>
#include <cstdint>
#include <cstddef>

// Problem constants
#define TT   512
#define BB   32
#define HH   1024
#define G4H  4096
#define NBLK 128           // persistent recurrent grid (co-resident)

// Recurrent smem layout
#define RS_U2    16384                 // uint2 count: 16w * 8ks * 4cg * 32lane
#define RS_BYTES (RS_U2 * 8)           // 131072
#define PSTR_B   552                   // part stride per b (floats), mod32==8 -> 2-way max
#define PART_BYTES (32 * PSTR_B * 4)   // 70656
#define SMEM_REC (RS_BYTES + PART_BYTES)  // 201728

// ---------------- scratch ----------------
__device__ float  g_xg[(size_t)TT * BB * G4H];        // input projection (standard [t][b][4H])
__device__ float4 g_xa[(size_t)TT * BB * HH / 4];     // packed-A input X (layer 0)
__device__ float4 g_x1[(size_t)TT * BB * HH / 4];     // packed-A layer-0 output
__device__ float2 g_wb[(size_t)G4H * HH / 2];         // packed-B weights (reused per layer)
__device__ float4 g_hb[2][8192];                      // packed-A hidden state, ping-pong
__device__ unsigned int          g_cnt1[8 * 32];
__device__ unsigned int          g_cnt2;
__device__ volatile unsigned int g_gen;

__device__ __forceinline__ float sigm(float x) {
    return 1.0f / (1.0f + expf(-x));
}

__device__ __forceinline__ uint32_t f2t(float x) {
    uint32_t r;
    asm("cvt.rna.tf32.f32 %0, %1;" : "=r"(r) : "f"(x));
    return r;
}
__device__ __forceinline__ float f2tf(float x) {
    return __uint_as_float(f2t(x));
}

__device__ __forceinline__ void mma1688(float c[4],
    uint32_t a0, uint32_t a1, uint32_t a2, uint32_t a3,
    uint32_t b0, uint32_t b1)
{
    asm volatile(
        "mma.sync.aligned.m16n8k8.row.col.f32.tf32.tf32.f32 "
        "{%0,%1,%2,%3}, {%4,%5,%6,%7}, {%8,%9}, {%0,%1,%2,%3};"
        : "+f"(c[0]), "+f"(c[1]), "+f"(c[2]), "+f"(c[3])
        : "r"(a0), "r"(a1), "r"(a2), "r"(a3), "r"(b0), "r"(b1));
}

// Two-level grid barrier: 8 groups x 16 blocks.
__device__ __forceinline__ void grid_barrier() {
    __syncthreads();
    if (threadIdx.x == 0) {
        __threadfence();
        unsigned int g = g_gen;
        unsigned int grp = blockIdx.x & 7u;
        if (atomicAdd(&g_cnt1[grp * 32], 1u) == 15u) {
            if (atomicAdd(&g_cnt2, 1u) == 7u) {
#pragma unroll
                for (int i = 0; i < 8; ++i) g_cnt1[i * 32] = 0u;
                g_cnt2 = 0u;
                __threadfence();
                g_gen = g + 1u;
            }
        }
        while (g_gen == g) { }
        __threadfence();
    }
    __syncthreads();
}

// =====================================================================
// Packing convert kernels
// =====================================================================
__global__ void __launch_bounds__(256) conv_pack_a(
    const float* __restrict__ X, float4* __restrict__ Ap)
{
    int s = blockIdx.x * 256 + threadIdx.x;
    int lane = s & 31, ks = (s >> 5) & 1, rg = (s >> 6) & 7, kt = (s >> 9) & 63, mb = s >> 15;
    int r0 = mb * 128 + rg * 16 + (lane >> 2);
    int c0 = kt * 16 + ks * 8 + (lane & 3);
    const float* p = X + (size_t)r0 * HH + c0;
    float4 v;
    v.x = f2tf(p[0]);
    v.y = f2tf(p[8 * HH]);
    v.z = f2tf(p[4]);
    v.w = f2tf(p[8 * HH + 4]);
    Ap[s] = v;
}

__global__ void __launch_bounds__(256) conv_pack_b(
    const float* __restrict__ W, float2* __restrict__ Bp)
{
    int s = blockIdx.x * 256 + threadIdx.x;
    int lane = s & 31, ks = (s >> 5) & 1, cg = (s >> 6) & 15, kt = (s >> 10) & 63, nb = s >> 16;
    int n  = nb * 128 + cg * 8 + (lane >> 2);
    int c0 = kt * 16 + ks * 8 + (lane & 3);
    const float* p = W + (size_t)n * HH + c0;
    Bp[s] = make_float2(f2tf(p[0]), f2tf(p[4]));
}

// =====================================================================
// Input projection GEMM from packed operands. 512 threads, 16 warps:
// warp (wm=warp>>2 in [0,4), wn=warp&3 in [0,4)); warp tile 32x32.
//   Y[m][n] = sum_k X[m][k]*W[n][k] + bi[n],  M=16384, N=4096, K=1024
// =====================================================================
__global__ void __launch_bounds__(512, 1) gemm_p(
    const float4* __restrict__ Ap, const float2* __restrict__ Bp,
    const float* __restrict__ bi, float* __restrict__ Y)
{
    const int tid  = threadIdx.x;
    const int warp = tid >> 5;
    const int lane = tid & 31;
    const int wm   = warp >> 2;
    const int wn   = warp & 3;
    const int nb   = blockIdx.x;
    const int mb   = blockIdx.y;

    const float4* Ab = Ap + (size_t)mb * 32768;
    const float2* Bb = Bp + (size_t)nb * 65536;

    float C[2][4][4];
#pragma unroll
    for (int a = 0; a < 2; ++a)
#pragma unroll
        for (int b = 0; b < 4; ++b)
#pragma unroll
            for (int c = 0; c < 4; ++c) C[a][b][c] = 0.0f;

    float4 Ar[2][2][2];
    float2 Brr[2][4][2];

#define LOADKT(kt, buf)                                                                  \
    {                                                                                    \
        _Pragma("unroll")                                                                \
        for (int mt = 0; mt < 2; ++mt)                                                   \
            _Pragma("unroll")                                                            \
            for (int ks = 0; ks < 2; ++ks)                                               \
                Ar[buf][mt][ks] = Ab[(((kt) * 8 + wm * 2 + mt) * 2 + ks) * 32 + lane];   \
        _Pragma("unroll")                                                                \
        for (int nt = 0; nt < 4; ++nt)                                                   \
            _Pragma("unroll")                                                            \
            for (int ks = 0; ks < 2; ++ks)                                               \
                Brr[buf][nt][ks] = Bb[(((kt) * 16 + wn * 4 + nt) * 2 + ks) * 32 + lane]; \
    }

#define COMPUTE(buf)                                                                     \
    {                                                                                    \
        _Pragma("unroll")                                                                \
        for (int ks = 0; ks < 2; ++ks)                                                   \
            _Pragma("unroll")                                                            \
            for (int mt = 0; mt < 2; ++mt) {                                             \
                float4 a = Ar[buf][mt][ks];                                              \
                uint32_t a0 = __float_as_uint(a.x), a1 = __float_as_uint(a.y);           \
                uint32_t a2 = __float_as_uint(a.z), a3 = __float_as_uint(a.w);           \
                _Pragma("unroll")                                                        \
                for (int nt = 0; nt < 4; ++nt) {                                         \
                    float2 b = Brr[buf][nt][ks];                                         \
                    mma1688(C[mt][nt], a0, a1, a2, a3,                                   \
                            __float_as_uint(b.x), __float_as_uint(b.y));                 \
                }                                                                        \
            }                                                                            \
    }

    LOADKT(0, 0);
#pragma unroll 1
    for (int kt = 0; kt < 64; kt += 2) {
        LOADKT(kt + 1, 1);
        COMPUTE(0);
        if (kt + 2 < 64) LOADKT(kt + 2, 0);
        COMPUTE(1);
    }
#undef LOADKT
#undef COMPUTE

    const int g = lane >> 2, tig = lane & 3;
#pragma unroll
    for (int mt = 0; mt < 2; ++mt) {
#pragma unroll
        for (int nt = 0; nt < 4; ++nt) {
            int row = mb * 128 + wm * 32 + mt * 16 + g;
            int col = nb * 128 + wn * 32 + nt * 8 + 2 * tig;
            float b0 = bi[col], b1 = bi[col + 1];
            *(float2*)(Y + (size_t)row * G4H + col) =
                make_float2(C[mt][nt][0] + b0, C[mt][nt][1] + b1);
            *(float2*)(Y + (size_t)(row + 8) * G4H + col) =
                make_float2(C[mt][nt][2] + b0, C[mt][nt][3] + b1);
        }
    }
}

// =====================================================================
// Persistent recurrent kernel: 512 threads / 16 warps.
// R pre-rounded to tf32 B-frags in SMEM (uint2, conflict-free LDS.64).
// Warp w owns k in [w*64, w*64+64). HB linear slot layout:
// slot for (k-octet kc, mt, lane) = (kc*2+mt)*32+lane.
// =====================================================================
__global__ void __launch_bounds__(512, 1) recurrent_tc(
    const float* __restrict__ xg,   // [T][B][4H]
    const float* __restrict__ R,    // [4H][H]
    const float* __restrict__ bh,   // [4H]
    const float* __restrict__ h0,   // [B][H]
    const float* __restrict__ c0,   // [B][H]
    float* __restrict__ outp,
    float* __restrict__ hT,         // [B][H]
    float* __restrict__ cT,         // [B][H]
    int mode)
{
    extern __shared__ char dsm[];
    uint2* Rs   = (uint2*)dsm;                  // [((w*8+ks)*4+cg)*32+lane]
    float* part = (float*)(dsm + RS_BYTES);     // part[b*PSTR_B + w*34 + j]

    const int tid  = threadIdx.x;
    const int w    = tid >> 5;
    const int lane = tid & 31;
    const int g    = lane >> 2;
    const int tig  = lane & 3;
    const int n0   = blockIdx.x * 8;

    // ---- Fill Rs (tf32-rounded B-fragments), once ----
#pragma unroll 4
    for (int it = 0; it < 32; ++it) {
        int s  = it * 512 + tid;
        int ls = s & 31, cg = (s >> 5) & 3, ks = (s >> 7) & 7, ww = s >> 10;
        int row = cg * HH + n0 + (ls >> 2);
        int col = ww * 64 + ks * 8 + (ls & 3);
        const float* rp = R + (size_t)row * HH + col;
        Rs[s] = make_uint2(f2t(__ldg(rp)), f2t(__ldg(rp + 4)));
    }

    // ---- Convert h0 into packed HB[0] (each block fills 64 slots) ----
    if (tid < 64) {
        int slot = blockIdx.x * 64 + tid;            // 0..8191
        int ls = slot & 31, mts = (slot >> 5) & 1;
        int kc = slot >> 6;                          // k-octet 0..127
        int k0 = kc * 8 + (ls & 3);
        int b0 = mts * 16 + (ls >> 2);
        float4 v;
        v.x = f2tf(h0[b0 * HH + k0]);
        v.y = f2tf(h0[(b0 + 8) * HH + k0]);
        v.z = f2tf(h0[b0 * HH + k0 + 4]);
        v.w = f2tf(h0[(b0 + 8) * HH + k0 + 4]);
        g_hb[0][slot] = v;
    }

    // ---- update-phase constants (ub aliased for tid>=256; writes guarded) ----
    const int ub = (tid >> 3) & 31;   // b 0..31
    const int un = tid & 7;           // n-offset 0..7
    const int hid = n0 + un;
    float bhv[4];
#pragma unroll
    for (int gg = 0; gg < 4; ++gg) bhv[gg] = bh[gg * HH + hid];
    float creg = c0[ub * HH + hid];

    // HB write address for (ub, hid)
    const int hw_kc = hid >> 3, hw_tig = hid & 3;
    const int hw_half = (hid >> 2) & 1;
    const int hw_mt = ub >> 4, hw_g = ub & 7, hw_rh = (ub >> 3) & 1;
    const int hb_slot = (hw_kc * 2 + hw_mt) * 32 + hw_g * 4 + hw_tig;
    const int hb_elem = hw_half * 2 + hw_rh;
    float* hb_w[2] = { (float*)&g_hb[0][hb_slot] + hb_elem,
                       (float*)&g_hb[1][hb_slot] + hb_elem };

    grid_barrier();   // Rs + HB[0] ready everywhere

    for (int t = 0; t < TT; ++t) {
        const float4* hp = g_hb[t & 1];

        // prefetch xg for update phase
        const float* xgt = xg + ((size_t)t * BB + ub) * G4H + hid;
        float xv[4];
#pragma unroll
        for (int gg = 0; gg < 4; ++gg) xv[gg] = __ldg(xgt + gg * HH);

        float Cr[2][4][4];
#pragma unroll
        for (int a = 0; a < 2; ++a)
#pragma unroll
            for (int b = 0; b < 4; ++b)
#pragma unroll
                for (int c = 0; c < 4; ++c) Cr[a][b][c] = 0.0f;

        // 4-deep pipelined h fragment loads (LDG.128, L2-coherent)
        float4 Ab[4][2];
#pragma unroll
        for (int p = 0; p < 4; ++p)
#pragma unroll
            for (int mt = 0; mt < 2; ++mt)
                Ab[p][mt] = __ldcg(&hp[((w * 8 + p) * 2 + mt) * 32 + lane]);

#pragma unroll
        for (int ks = 0; ks < 8; ++ks) {
            const int pb = ks & 3;
            float4 a0 = Ab[pb][0];
            float4 a1 = Ab[pb][1];
            if (ks + 4 < 8) {
#pragma unroll
                for (int mt = 0; mt < 2; ++mt)
                    Ab[pb][mt] = __ldcg(&hp[((w * 8 + (ks + 4)) * 2 + mt) * 32 + lane]);
            }
            uint32_t u00 = __float_as_uint(a0.x), u01 = __float_as_uint(a0.y);
            uint32_t u02 = __float_as_uint(a0.z), u03 = __float_as_uint(a0.w);
            uint32_t u10 = __float_as_uint(a1.x), u11 = __float_as_uint(a1.y);
            uint32_t u12 = __float_as_uint(a1.z), u13 = __float_as_uint(a1.w);
#pragma unroll
            for (int cg = 0; cg < 4; ++cg) {
                uint2 bv = Rs[((w * 8 + ks) * 4 + cg) * 32 + lane];
                mma1688(Cr[0][cg], u00, u01, u02, u03, bv.x, bv.y);
                mma1688(Cr[1][cg], u10, u11, u12, u13, bv.x, bv.y);
            }
        }

        // store partials: part[b*PSTR_B + w*34 + j], float2
#pragma unroll
        for (int mt = 0; mt < 2; ++mt) {
#pragma unroll
            for (int cg = 0; cg < 4; ++cg) {
                int b = mt * 16 + g;
                int j = cg * 8 + 2 * tig;
                *(float2*)&part[b * PSTR_B + w * 34 + j] =
                    make_float2(Cr[mt][cg][0], Cr[mt][cg][1]);
                *(float2*)&part[(b + 8) * PSTR_B + w * 34 + j] =
                    make_float2(Cr[mt][cg][2], Cr[mt][cg][3]);
            }
        }
        __syncthreads();

        // reduce over 16 warps + gate math (warps 0-7 only). gates: i, o, z, f
        if (tid < 256) {
            float gate[4];
#pragma unroll
            for (int gg = 0; gg < 4; ++gg) {
                float s = xv[gg] + bhv[gg];
#pragma unroll
                for (int wi = 0; wi < 16; ++wi)
                    s += part[ub * PSTR_B + wi * 34 + gg * 8 + un];
                gate[gg] = sigm(s);
            }
            creg = creg * gate[3] + gate[2] - gate[0];   // c = c*f + z - i
            float hval = sigm(creg) - gate[1];           // h = sigm(c) - o

            if (mode == 0) {
                // packed-A layout for layer-1 gemm (tf32-rounded)
                int m = t * BB + ub;
                int mb = m >> 7, r = m & 127;
                int rg_ = r >> 4, rh_ = (r >> 3) & 1, g_ = r & 7;
                int kt_ = hid >> 4, ks_ = (hid >> 3) & 1;
                int half_ = (hid >> 2) & 1, tig_ = hid & 3;
                size_t slot = (((size_t)(mb * 64 + kt_) * 8 + rg_) * 2 + ks_) * 32
                              + g_ * 4 + tig_;
                outp[slot * 4 + half_ * 2 + rh_] = f2tf(hval);
            } else {
                outp[((size_t)t * BB + ub) * HH + hid] = hval;
            }

            // HB store for next step (tf32-rounded)
            *hb_w[(t + 1) & 1] = f2tf(hval);

            if (t == TT - 1) {
                hT[ub * HH + hid] = hval;
                cT[ub * HH + hid] = creg;
            }
        }

        grid_barrier();
    }
}

// ---------------- launch ----------------
extern "C" void kernel_launch(void* const* d_in, const int* in_sizes, int n_in,
                              void* d_out, int out_size)
{
    (void)in_sizes; (void)n_in; (void)out_size;
    const float* x   = (const float*)d_in[0];
    const float* h0  = (const float*)d_in[1];
    const float* c0  = (const float*)d_in[2];
    const float* W0  = (const float*)d_in[3];
    const float* R0  = (const float*)d_in[4];
    const float* bi0 = (const float*)d_in[5];
    const float* bh0 = (const float*)d_in[6];
    const float* W1  = (const float*)d_in[7];
    const float* R1  = (const float*)d_in[8];
    const float* bi1 = (const float*)d_in[9];
    const float* bh1 = (const float*)d_in[10];

    float* out = (float*)d_out;
    float* hT  = out + (size_t)TT * BB * HH;
    float* cT  = hT + (size_t)2 * BB * HH;

    float*  xg = nullptr;  cudaGetSymbolAddress((void**)&xg, g_xg);
    float4* xa = nullptr;  cudaGetSymbolAddress((void**)&xa, g_xa);
    float4* x1 = nullptr;  cudaGetSymbolAddress((void**)&x1, g_x1);
    float2* wb = nullptr;  cudaGetSymbolAddress((void**)&wb, g_wb);

    // Unconditional (no static guards): idempotent, non-stream API, capture-safe.
    cudaFuncSetAttribute(recurrent_tc,
                         cudaFuncAttributeMaxDynamicSharedMemorySize, SMEM_REC);

    const int aslots = TT * BB * HH / 4;   // 4,194,304
    const int bslots = G4H * HH / 2;       // 2,097,152
    dim3 ggrid(G4H / 128, (TT * BB) / 128);  // (32, 128)

    // Layer 0
    conv_pack_a<<<aslots / 256, 256>>>(x, xa);
    conv_pack_b<<<bslots / 256, 256>>>(W0, wb);
    gemm_p<<<ggrid, 512>>>(xa, wb, bi0, xg);
    recurrent_tc<<<NBLK, 512, SMEM_REC>>>(xg, R0, bh0, h0, c0, (float*)x1, hT, cT, 0);
    // Layer 1
    conv_pack_b<<<bslots / 256, 256>>>(W1, wb);
    gemm_p<<<ggrid, 512>>>(x1, wb, bi1, xg);
    recurrent_tc<<<NBLK, 512, SMEM_REC>>>(xg, R1, bh1, h0 + BB * HH, c0 + BB * HH,
                                          out, hT + BB * HH, cT + BB * HH, 1);
}

// round 9
// speedup vs baseline: 1.4060x; 1.4060x over previous
#include <cuda_runtime.h>
#include <cuda_fp16.h>
#include <cstdint>
#include <cstddef>

// Problem constants
#define TT   512
#define BB   32
#define HH   1024
#define G4H  4096
#define NBLK 128           // persistent recurrent grid (co-resident)

// ---------------- scratch ----------------
__device__ float g_xg[(size_t)TT * BB * G4H];     // input projection (fp32 [t][b][4H])
__device__ uint4 g_xa[2097152];                   // packed-A fp16 X (layer 0), 32MB
__device__ uint4 g_x1[2097152];                   // packed-A fp16 layer-0 output, 32MB
__device__ uint4 g_wb[1048576];                   // packed-B fp16 weights (16MB), per layer
__device__ uint4 g_hb[2][4096];                   // packed-A fp16 hidden state, ping-pong (2x64KB)
__device__ unsigned int          g_cnt1[8 * 32];
__device__ unsigned int          g_cnt2;
__device__ volatile unsigned int g_gen;

__device__ __forceinline__ float sigm(float x) {
    return 1.0f / (1.0f + expf(-x));
}

// pack two floats into one fp16x2 register (lo = first arg)
__device__ __forceinline__ uint32_t h2pack(float lo, float hi) {
    __half2 h = __floats2half2_rn(lo, hi);
    return *(uint32_t*)&h;
}

// fp16 tensor-core mma, fp32 accumulate
__device__ __forceinline__ void mma16816(float c[4],
    uint32_t a0, uint32_t a1, uint32_t a2, uint32_t a3,
    uint32_t b0, uint32_t b1)
{
    asm volatile(
        "mma.sync.aligned.m16n8k16.row.col.f32.f16.f16.f32 "
        "{%0,%1,%2,%3}, {%4,%5,%6,%7}, {%8,%9}, {%0,%1,%2,%3};"
        : "+f"(c[0]), "+f"(c[1]), "+f"(c[2]), "+f"(c[3])
        : "r"(a0), "r"(a1), "r"(a2), "r"(a3), "r"(b0), "r"(b1));
}

// Two-level grid barrier: 8 groups x 16 blocks. All NBLK blocks co-resident.
__device__ __forceinline__ void grid_barrier() {
    __syncthreads();
    if (threadIdx.x == 0) {
        __threadfence();
        unsigned int g = g_gen;
        unsigned int grp = blockIdx.x & 7u;
        if (atomicAdd(&g_cnt1[grp * 32], 1u) == 15u) {
            if (atomicAdd(&g_cnt2, 1u) == 7u) {
#pragma unroll
                for (int i = 0; i < 8; ++i) g_cnt1[i * 32] = 0u;
                g_cnt2 = 0u;
                __threadfence();
                g_gen = g + 1u;
            }
        }
        while (g_gen == g) { }
        __threadfence();
    }
    __syncthreads();
}

// =====================================================================
// Packing converters (fp32 -> fp16 mma fragments)
// A slot s = ((mb*64+kt)*8+rg)*32+lane : uint4 {a0,a1,a2,a3} for
//   rows mb*128+rg*16+{g,g+8}, k = kt*16+{2tig,2tig+1,8+2tig,9+2tig}
// =====================================================================
__global__ void __launch_bounds__(256) conv_pack_a(
    const float* __restrict__ X, uint4* __restrict__ Ap)
{
    int s = blockIdx.x * 256 + threadIdx.x;
    int lane = s & 31, rg = (s >> 5) & 7, kt = (s >> 8) & 63, mb = s >> 14;
    int g = lane >> 2, tig = lane & 3;
    int r0 = mb * 128 + rg * 16 + g;
    int k0 = kt * 16 + 2 * tig;
    const float* p0 = X + (size_t)r0 * HH;
    const float* p1 = X + (size_t)(r0 + 8) * HH;
    uint4 v;
    v.x = h2pack(p0[k0],     p0[k0 + 1]);
    v.y = h2pack(p1[k0],     p1[k0 + 1]);
    v.z = h2pack(p0[k0 + 8], p0[k0 + 9]);
    v.w = h2pack(p1[k0 + 8], p1[k0 + 9]);
    Ap[s] = v;
}

// B slot (uint2) s = ((nb*64+kt)*16+cg)*32+lane :
//   n = nb*128+cg*8+g, b0 = {W[n][kt*16+2tig], +1}, b1 = {+8, +9}
__global__ void __launch_bounds__(256) conv_pack_b(
    const float* __restrict__ W, uint2* __restrict__ Bp)
{
    int s = blockIdx.x * 256 + threadIdx.x;
    int lane = s & 31, cg = (s >> 5) & 15, kt = (s >> 9) & 63, nb = s >> 15;
    int g = lane >> 2, tig = lane & 3;
    int n  = nb * 128 + cg * 8 + g;
    int k0 = kt * 16 + 2 * tig;
    const float* p = W + (size_t)n * HH;
    Bp[s] = make_uint2(h2pack(p[k0], p[k0 + 1]), h2pack(p[k0 + 8], p[k0 + 9]));
}

// =====================================================================
// Input projection GEMM, fp16 tensor cores, cp.async 8-deep smem pipeline.
//   Y[m][n] = sum_k X[m][k]*W[n][k] + bi[n],  M=16384, N=4096, K=1024
//   512 threads, 16 warps (wm 0..3 x wn 0..3), warp tile 32x32.
//   smem: 8 stages x (A 4KB + B 4KB) = 64KB dynamic.
// =====================================================================
#define STG 8
#define GEMM_SMEM (STG * 512 * 16)

__global__ void __launch_bounds__(512, 1) gemm_h(
    const uint4* __restrict__ Ap, const uint4* __restrict__ Bp4,
    const float* __restrict__ bi, float* __restrict__ Y)
{
    extern __shared__ uint4 sm[];   // [stage*512 + (A:0..255 | B:256..511)]

    const int tid  = threadIdx.x;
    const int warp = tid >> 5;
    const int lane = tid & 31;
    const int wm   = warp >> 2;
    const int wn   = warp & 3;
    const int nb   = blockIdx.x;
    const int mb   = blockIdx.y;

    const uint4* Ab4 = Ap  + (size_t)mb * 16384;
    const uint4* Bb4 = Bp4 + (size_t)nb * 16384;

    // per-thread cp.async source/dest partition
    const int j = tid & 255;
    const bool isA = tid < 256;
    const uint4* srcBase = isA ? Ab4 : Bb4;
    const int dstOff = (isA ? 0 : 256) + j;

    float C[2][4][4];
#pragma unroll
    for (int a = 0; a < 2; ++a)
#pragma unroll
        for (int b = 0; b < 4; ++b)
#pragma unroll
            for (int c = 0; c < 4; ++c) C[a][b][c] = 0.0f;

#define ISSUE(kt)                                                                   \
    {                                                                               \
        uint32_t d = (uint32_t)__cvta_generic_to_shared(                            \
            &sm[((kt) & (STG - 1)) * 512 + dstOff]);                                \
        const uint4* s_ = srcBase + (size_t)(kt) * 256 + j;                         \
        asm volatile("cp.async.cg.shared.global [%0], [%1], 16;\n" :: "r"(d), "l"(s_)); \
        asm volatile("cp.async.commit_group;\n");                                   \
    }

#pragma unroll
    for (int kt = 0; kt < STG - 1; ++kt) ISSUE(kt);

#pragma unroll 1
    for (int kt = 0; kt < 64; ++kt) {
        asm volatile("cp.async.wait_group %0;\n" :: "n"(STG - 2) : "memory");
        __syncthreads();
        if (kt + STG - 1 < 64) ISSUE(kt + STG - 1);

        const int st = kt & (STG - 1);
        uint4 au[2];
#pragma unroll
        for (int mt = 0; mt < 2; ++mt)
            au[mt] = sm[st * 512 + (wm * 2 + mt) * 32 + lane];
        const uint2* b2 = (const uint2*)(sm + st * 512 + 256);
        uint2 bu[4];
#pragma unroll
        for (int cg = 0; cg < 4; ++cg)
            bu[cg] = b2[(wn * 4 + cg) * 32 + lane];
#pragma unroll
        for (int mt = 0; mt < 2; ++mt)
#pragma unroll
            for (int cg = 0; cg < 4; ++cg)
                mma16816(C[mt][cg], au[mt].x, au[mt].y, au[mt].z, au[mt].w,
                         bu[cg].x, bu[cg].y);
    }
#undef ISSUE

    const int g = lane >> 2, tig = lane & 3;
#pragma unroll
    for (int mt = 0; mt < 2; ++mt) {
#pragma unroll
        for (int cg = 0; cg < 4; ++cg) {
            int row = mb * 128 + wm * 32 + mt * 16 + g;
            int col = nb * 128 + wn * 32 + cg * 8 + 2 * tig;
            float b0 = bi[col], b1 = bi[col + 1];
            *(float2*)(Y + (size_t)row * G4H + col) =
                make_float2(C[mt][cg][0] + b0, C[mt][cg][1] + b1);
            *(float2*)(Y + (size_t)(row + 8) * G4H + col) =
                make_float2(C[mt][cg][2] + b0, C[mt][cg][3] + b1);
        }
    }
}

// =====================================================================
// Persistent recurrent kernel: 256 threads / 8 warps, fp16 operands.
// Block owns 8 n-indices -> 32 gate columns. Warp w: k in [w*128,(w+1)*128),
// 8 mma-ksteps of 16. R fp16 fragments register-resident (64 regs).
// h in g_hb as packed fp16 A-fragments: slot (kt,mt,lane)=(kt*2+mt)*32+lane.
// =====================================================================
__global__ void __launch_bounds__(256, 1) recurrent_h(
    const float* __restrict__ xg,   // [T][B][4H]
    const float* __restrict__ R,    // [4H][H]
    const float* __restrict__ bh,   // [4H]
    const float* __restrict__ h0,   // [B][H]
    const float* __restrict__ c0,   // [B][H]
    float* __restrict__ outp,
    float* __restrict__ hT,         // [B][H]
    float* __restrict__ cT,         // [B][H]
    int mode)
{
    __shared__ float part[32 * 296];   // part[b][w][j] : b*296 + w*37 + j

    const int tid  = threadIdx.x;
    const int w    = tid >> 5;
    const int lane = tid & 31;
    const int g    = lane >> 2;
    const int tig  = lane & 3;
    const int n0   = blockIdx.x * 8;

    // ---- Preload R fp16 B-fragments into registers ----
    uint32_t Br[4][8][2];
#pragma unroll
    for (int cg = 0; cg < 4; ++cg) {
        const float* rp = R + (size_t)(cg * HH + n0 + g) * HH + w * 128 + 2 * tig;
#pragma unroll
        for (int ks = 0; ks < 8; ++ks) {
            const float* q = rp + ks * 16;
            Br[cg][ks][0] = h2pack(__ldg(q),     __ldg(q + 1));
            Br[cg][ks][1] = h2pack(__ldg(q + 8), __ldg(q + 9));
        }
    }

    // ---- Convert h0 into packed fp16 HB[0] (32 slots per block) ----
    if (tid < 32) {
        int slot = blockIdx.x * 32 + tid;            // 0..4095
        int ls = slot & 31, mts = (slot >> 5) & 1, kt = slot >> 6;
        int gs = ls >> 2, ts = ls & 3;
        int r0 = mts * 16 + gs;
        int k0 = kt * 16 + 2 * ts;
        const float* p0 = h0 + (size_t)r0 * HH;
        const float* p1 = h0 + (size_t)(r0 + 8) * HH;
        uint4 v;
        v.x = h2pack(p0[k0],     p0[k0 + 1]);
        v.y = h2pack(p1[k0],     p1[k0 + 1]);
        v.z = h2pack(p0[k0 + 8], p0[k0 + 9]);
        v.w = h2pack(p1[k0 + 8], p1[k0 + 9]);
        g_hb[0][slot] = v;
    }

    // ---- update-phase constants ----
    const int ub = tid >> 3;   // b 0..31
    const int un = tid & 7;    // n-offset 0..7
    const int hid = n0 + un;
    float bhv[4];
#pragma unroll
    for (int gg = 0; gg < 4; ++gg) bhv[gg] = bh[gg * HH + hid];
    float creg = c0[ub * HH + hid];

    // fp16 h write address for (ub, hid) inside HB slot
    const int hw_mt = ub >> 4, hw_row16 = ub & 15;
    const int hw_g = hw_row16 & 7, hw_rh = hw_row16 >> 3;
    const int hw_kt = hid >> 4, hw_k15 = hid & 15;
    const int hw_kh = hw_k15 >> 3, hw_tig = (hw_k15 & 7) >> 1, hw_hs = hw_k15 & 1;
    const int hb_slot = (hw_kt * 2 + hw_mt) * 32 + hw_g * 4 + hw_tig;
    const int hb_half = (hw_kh * 2 + hw_rh) * 2 + hw_hs;   // half index within uint4
    __half* hb_w[2] = { (__half*)&g_hb[0][hb_slot] + hb_half,
                        (__half*)&g_hb[1][hb_slot] + hb_half };

    grid_barrier();   // HB[0] ready everywhere

    for (int t = 0; t < TT; ++t) {
        const uint4* hp = g_hb[t & 1];

        // prefetch xg for update phase
        const float* xgt = xg + ((size_t)t * BB + ub) * G4H + hid;
        float xv[4];
#pragma unroll
        for (int gg = 0; gg < 4; ++gg) xv[gg] = __ldg(xgt + gg * HH);

        float Cr[2][4][4];
#pragma unroll
        for (int a = 0; a < 2; ++a)
#pragma unroll
            for (int b = 0; b < 4; ++b)
#pragma unroll
                for (int c = 0; c < 4; ++c) Cr[a][b][c] = 0.0f;

        // 4-deep pipelined h fragment loads (LDG.128, L2-coherent)
        uint4 Ab[4][2];
#pragma unroll
        for (int p = 0; p < 4; ++p)
#pragma unroll
            for (int mt = 0; mt < 2; ++mt)
                Ab[p][mt] = __ldcg(&hp[((w * 8 + p) * 2 + mt) * 32 + lane]);

#pragma unroll
        for (int ks = 0; ks < 8; ++ks) {
            const int pb = ks & 3;
            uint4 a0 = Ab[pb][0];
            uint4 a1 = Ab[pb][1];
            if (ks + 4 < 8) {
#pragma unroll
                for (int mt = 0; mt < 2; ++mt)
                    Ab[pb][mt] = __ldcg(&hp[((w * 8 + (ks + 4)) * 2 + mt) * 32 + lane]);
            }
#pragma unroll
            for (int cg = 0; cg < 4; ++cg) {
                mma16816(Cr[0][cg], a0.x, a0.y, a0.z, a0.w, Br[cg][ks][0], Br[cg][ks][1]);
                mma16816(Cr[1][cg], a1.x, a1.y, a1.z, a1.w, Br[cg][ks][0], Br[cg][ks][1]);
            }
        }

        // store partials to smem (SCALAR stores: stride 37 is odd -> no float2!)
#pragma unroll
        for (int mt = 0; mt < 2; ++mt) {
#pragma unroll
            for (int cg = 0; cg < 4; ++cg) {
                int b = mt * 16 + g;
                int jj = cg * 8 + 2 * tig;
                part[b * 296 + w * 37 + jj]           = Cr[mt][cg][0];
                part[b * 296 + w * 37 + jj + 1]       = Cr[mt][cg][1];
                part[(b + 8) * 296 + w * 37 + jj]     = Cr[mt][cg][2];
                part[(b + 8) * 296 + w * 37 + jj + 1] = Cr[mt][cg][3];
            }
        }
        __syncthreads();

        // reduce over 8 warps + gate math. gates order: i, o, z, f
        float gate[4];
#pragma unroll
        for (int gg = 0; gg < 4; ++gg) {
            float s = xv[gg] + bhv[gg];
#pragma unroll
            for (int wi = 0; wi < 8; ++wi)
                s += part[ub * 296 + wi * 37 + gg * 8 + un];
            gate[gg] = sigm(s);
        }
        creg = creg * gate[3] + gate[2] - gate[0];   // c = c*f + z - i
        float hval = sigm(creg) - gate[1];           // h = sigm(c) - o

        if (mode == 0) {
            // packed-A fp16 layout for layer-1 gemm
            int m = t * BB + ub;
            int mb = m >> 7, r = m & 127;
            int rg_ = r >> 4, row16 = r & 15;
            int g_ = row16 & 7, rh_ = row16 >> 3;
            size_t slot = ((size_t)(mb * 64 + hw_kt) * 8 + rg_) * 32 + g_ * 4 + hw_tig;
            ((__half*)&((uint4*)outp)[slot])[(hw_kh * 2 + rh_) * 2 + hw_hs] =
                __float2half_rn(hval);
        } else {
            outp[((size_t)t * BB + ub) * HH + hid] = hval;
        }

        // fp16 HB store for next step
        *hb_w[(t + 1) & 1] = __float2half_rn(hval);

        if (t == TT - 1) {
            hT[ub * HH + hid] = hval;
            cT[ub * HH + hid] = creg;
        }

        grid_barrier();
    }
}

// ---------------- launch ----------------
extern "C" void kernel_launch(void* const* d_in, const int* in_sizes, int n_in,
                              void* d_out, int out_size)
{
    (void)in_sizes; (void)n_in; (void)out_size;
    const float* x   = (const float*)d_in[0];
    const float* h0  = (const float*)d_in[1];
    const float* c0  = (const float*)d_in[2];
    const float* W0  = (const float*)d_in[3];
    const float* R0  = (const float*)d_in[4];
    const float* bi0 = (const float*)d_in[5];
    const float* bh0 = (const float*)d_in[6];
    const float* W1  = (const float*)d_in[7];
    const float* R1  = (const float*)d_in[8];
    const float* bi1 = (const float*)d_in[9];
    const float* bh1 = (const float*)d_in[10];

    float* out = (float*)d_out;
    float* hT  = out + (size_t)TT * BB * HH;
    float* cT  = hT + (size_t)2 * BB * HH;

    float* xg = nullptr;  cudaGetSymbolAddress((void**)&xg, g_xg);
    uint4* xa = nullptr;  cudaGetSymbolAddress((void**)&xa, g_xa);
    uint4* x1 = nullptr;  cudaGetSymbolAddress((void**)&x1, g_x1);
    uint4* wb = nullptr;  cudaGetSymbolAddress((void**)&wb, g_wb);

    cudaFuncSetAttribute(gemm_h, cudaFuncAttributeMaxDynamicSharedMemorySize, GEMM_SMEM);

    dim3 ggrid(G4H / 128, (TT * BB) / 128);  // (32, 128)

    // Layer 0
    conv_pack_a<<<2097152 / 256, 256>>>(x, xa);
    conv_pack_b<<<1048576 / 256, 256>>>(W0, (uint2*)wb);
    gemm_h<<<ggrid, 512, GEMM_SMEM>>>(xa, wb, bi0, xg);
    recurrent_h<<<NBLK, 256>>>(xg, R0, bh0, h0, c0, (float*)x1, hT, cT, 0);
    // Layer 1
    conv_pack_b<<<1048576 / 256, 256>>>(W1, (uint2*)wb);
    gemm_h<<<ggrid, 512, GEMM_SMEM>>>(x1, wb, bi1, xg);
    recurrent_h<<<NBLK, 256>>>(xg, R1, bh1, h0 + BB * HH, c0 + BB * HH,
                               out, hT + BB * HH, cT + BB * HH, 1);
}